// round 17
// baseline (speedup 1.0000x reference)
#include <cuda_runtime.h>
#include <cstdint>

// Problem constants
#define N_ 64
#define L_ 512
#define T_ 128
#define D_ 1024
#define D4 (D_ / 4)          // 256 float4 per row
#define L4 (L_ / 4)          // 128 float4 per att row
#define NPAIRS 4             // warp-pairs per CTA (8 warps, 256 threads)
#define ROWS_PER_PAIR 8
#define TILE_ROWS (NPAIRS * ROWS_PER_PAIR)    // 32
#define NTILES (L_ / TILE_ROWS)               // 16

// Scratch (allocation-free device globals; zero-initialized at load, and
// pass2 restores accumulators to zero each launch -> no zero kernel).
__device__ float g_e[N_][L_];       // unnormalized exp(scores) (overwritten)
__device__ float g_g[N_][D_];       // atomically accumulated weighted sums
__device__ float g_z16[N_][16];     // 16 replicas of sum-of-exps (one per pass2 CTA)

// ---------------------------------------------------------------------------
// Pass 1: ONE DRAM read of f1. Two-warp teams, each warp holds a HALF row.
// TWO rows per iteration -> one pair-barrier per 2 rows (4 barriers total),
// 8 LDG.128 in flight. e = exp(dot): no max-shift needed (scores are O(1));
// exp-weighted partials are associative -> REDG combine into g_g / g_z16.
// Grid (NTILES=16, N=64) = 1024 CTAs x 256 threads.
// ---------------------------------------------------------------------------
__global__ void __launch_bounds__(256) pass1_kernel(
    const float* __restrict__ f1, const float* __restrict__ w)
{
    __shared__ float4 wsh[D4];                   // 4 KB
    __shared__ float4 accsh[NPAIRS][D4];         // 16 KB
    __shared__ float2 sdot[2][8];                // double-buffered partial dot pairs
    __shared__ float  zsh[NPAIRS];

    int tid = threadIdx.x, lane = tid & 31, warp = tid >> 5;
    int pair = warp >> 1, h = warp & 1;          // h: which half of the row
    wsh[tid] = reinterpret_cast<const float4*>(w)[tid];
    __syncthreads();

    int tile = blockIdx.x, n = blockIdx.y;
    int row0 = tile * TILE_ROWS + pair * ROWS_PER_PAIR;
    const float4* base = reinterpret_cast<const float4*>(f1)
                         + ((size_t)n * L_ + row0) * D4 + h * (D4 / 2);

    float4 acc[4];
#pragma unroll
    for (int j = 0; j < 4; ++j) acc[j] = make_float4(0.f, 0.f, 0.f, 0.f);
    float zacc = 0.f;

#pragma unroll 1
    for (int r = 0; r < ROWS_PER_PAIR; r += 2) {
        const float4* p0 = base + (size_t)r * D4;
        const float4* p1 = p0 + D4;
        float4 x0[4], x1[4];
#pragma unroll
        for (int j = 0; j < 4; ++j) x0[j] = p0[lane + 32 * j];
#pragma unroll
        for (int j = 0; j < 4; ++j) x1[j] = p1[lane + 32 * j];

        float d0 = 0.f, d1 = 0.f;
#pragma unroll
        for (int j = 0; j < 4; ++j) {
            float4 ww = wsh[h * (D4 / 2) + lane + 32 * j];
            d0 += x0[j].x * ww.x + x0[j].y * ww.y + x0[j].z * ww.z + x0[j].w * ww.w;
            d1 += x1[j].x * ww.x + x1[j].y * ww.y + x1[j].z * ww.z + x1[j].w * ww.w;
        }
#pragma unroll
        for (int o = 16; o > 0; o >>= 1) {
            d0 += __shfl_xor_sync(0xffffffffu, d0, o);
            d1 += __shfl_xor_sync(0xffffffffu, d1, o);
        }
        int buf = (r >> 1) & 1;
        if (lane == 0) sdot[buf][warp] = make_float2(d0, d1);
        // pair-private barrier: 64 threads, id = pair+1 (ids 1..4)
        asm volatile("bar.sync %0, 64;" :: "r"(pair + 1) : "memory");

        float2 da = sdot[buf][pair * 2];
        float2 db = sdot[buf][pair * 2 + 1];
        float e0 = __expf(da.x + db.x);
        float e1 = __expf(da.y + db.y);
        if (h == 0) {
            zacc += e0 + e1;
            if (lane == 0) {
                g_e[n][row0 + r]     = e0;
                g_e[n][row0 + r + 1] = e1;
            }
        }
#pragma unroll
        for (int j = 0; j < 4; ++j) {
            acc[j].x = fmaf(e0, x0[j].x, fmaf(e1, x1[j].x, acc[j].x));
            acc[j].y = fmaf(e0, x0[j].y, fmaf(e1, x1[j].y, acc[j].y));
            acc[j].z = fmaf(e0, x0[j].z, fmaf(e1, x1[j].z, acc[j].z));
            acc[j].w = fmaf(e0, x0[j].w, fmaf(e1, x1[j].w, acc[j].w));
        }
    }

#pragma unroll
    for (int j = 0; j < 4; ++j)
        accsh[pair][h * (D4 / 2) + lane + 32 * j] = acc[j];
    if (h == 0 && lane == 0) zsh[pair] = zacc;
    __syncthreads();

    // cross-pair reduce then REDG into global accumulators
    float4 t = accsh[0][tid];
#pragma unroll
    for (int k = 1; k < NPAIRS; ++k) {
        float4 a = accsh[k][tid];
        t.x += a.x; t.y += a.y; t.z += a.z; t.w += a.w;
    }
    float* gcol = &g_g[n][tid * 4];
    atomicAdd(gcol + 0, t.x);
    atomicAdd(gcol + 1, t.y);
    atomicAdd(gcol + 2, t.z);
    atomicAdd(gcol + 3, t.w);
    if (tid < 16)   // 16 z-replicas, one per future pass2 CTA
        atomicAdd(&g_z16[n][tid],
                  (zsh[0] + zsh[1]) + (zsh[2] + zsh[3]));
}

// ---------------------------------------------------------------------------
// Pass 2: pure broadcast + self-clean, 16-way COLUMN split, DEFAULT store
// policy (no __stcs). Grid (N=64, 16) x 256 threads; CTA (n,c) exclusively
// owns D-16th c of fhat and L-16th c of att for all 128 T-rows.
// 12 STG.128 per thread.
// ---------------------------------------------------------------------------
__global__ void __launch_bounds__(256) pass2_kernel(
    float* __restrict__ fhat, float* __restrict__ att)
{
    __shared__ float4 gsh[16];                    // 256 B: normalized D-16th
    __shared__ __align__(16) float esh[32];       // 128 B: normalized L-16th

    int n = blockIdx.x, c = blockIdx.y;
    int tid = threadIdx.x;

    float inv = __frcp_rn(g_z16[n][c]);

    if (tid < 16) {
        float4 g = reinterpret_cast<const float4*>(&g_g[n][0])[c * 16 + tid];
        g.x *= inv; g.y *= inv; g.z *= inv; g.w *= inv;
        gsh[tid] = g;
        reinterpret_cast<float4*>(&g_g[n][0])[c * 16 + tid] =
            make_float4(0.f, 0.f, 0.f, 0.f);       // self-clean own slice
    } else if (tid < 48) {
        int l = c * 32 + (tid - 16);
        esh[tid - 16] = g_e[n][l] * inv;           // g_e overwritten: no clean
    } else if (tid == 48) {
        g_z16[n][c] = 0.f;                         // clean own replica
    }
    __syncthreads();

    // fhat[n, t, c*64 : c*64+64]: 16 f4 cols x 128 t rows = 2048 f4, 8/thread
    {
        int f  = tid & 15;
        int tg = tid >> 4;        // 16 row groups; t = tg + 16*i
        float4 gval = gsh[f];
        float4* p = reinterpret_cast<float4*>(fhat)
                    + (size_t)n * T_ * D4 + (size_t)tg * D4 + c * 16 + f;
#pragma unroll
        for (int i = 0; i < 8; ++i) {
            *p = gval;
            p += 16 * D4;
        }
    }

    // att[n, t, c*32 : c*32+32]: 8 f4 cols x 128 t rows = 1024 f4, 4/thread
    {
        int f  = tid & 7;
        int tg = tid >> 3;        // 32 row groups; t = tg + 32*i
        float4 aval = reinterpret_cast<const float4*>(esh)[f];
        float4* q = reinterpret_cast<float4*>(att)
                    + (size_t)n * T_ * L4 + (size_t)tg * L4 + c * 8 + f;
#pragma unroll
        for (int i = 0; i < 4; ++i) {
            *q = aval;
            q += 32 * L4;
        }
    }
}

// ---------------------------------------------------------------------------
extern "C" void kernel_launch(void* const* d_in, const int* in_sizes, int n_in,
                              void* d_out, int out_size)
{
    const float* f1 = (const float*)d_in[0];  // [N,L,D]
    // d_in[1] = feature_2 : unused (softmax shift-invariance cancels it)
    const float* w  = (const float*)d_in[2];  // [D]
    // d_in[3] = b : unused (cancels in softmax)

    float* fhat = (float*)d_out;                         // [N,T,D]
    float* att  = (float*)d_out + (size_t)N_ * T_ * D_;  // [N,T,L]

    pass1_kernel<<< dim3(NTILES, N_), 256 >>> (f1, w);
    pass2_kernel<<< dim3(N_, 16), 256 >>> (fhat, att);
}